// round 14
// baseline (speedup 1.0000x reference)
#include <cuda_runtime.h>
#include <cuda_bf16.h>

#define L_SEQ 96
#define N_V   207
#define N_B   4
#define N_C   512
#define TOPK  4
#define N_UNITS 4          // channel quarters per (b,v)
#define TPB_T 192          // 6 warps: warp w = m-tile rows [16w, 16w+16)
#define RS    20           // smem row stride in u32 (40 bf16): (20g+t)%32 all-distinct

// scratch (device globals: no allocation allowed)
__device__ float g_mv4[N_B * N_V * N_UNITS * L_SEQ];
__device__ int   g_idx[N_V * TOPK];
__device__ float g_prob[N_B * N_V * TOPK];

// ---------------------------------------------------------------------------
// corr via warp-level bf16 HMMA (mma.sync, generic PTX -> compiles for
// compute_103). One CTA per (b, v, channel-quarter): C = Q·K^T (96x96, K=128
// channels per unit), fp32 accum. fp32 inputs split x = xh + xl (bf16 each);
// 3 passes hh + hl + lh leave only the ll term (~2^-15/product) -> top-k gaps
// exceed the induced gm error by ~5000x. Epilogue: circular-diagonal sums
// mean_value[l] = sum_t C[t][(t-l)%96], accumulated per-quarter into g_mv4.
// ---------------------------------------------------------------------------
__device__ __forceinline__ void mma_bf16(float* c,
                                         unsigned a0, unsigned a1, unsigned a2, unsigned a3,
                                         unsigned b0, unsigned b1) {
    asm volatile(
        "mma.sync.aligned.m16n8k16.row.col.f32.bf16.bf16.f32 "
        "{%0,%1,%2,%3}, {%4,%5,%6,%7}, {%8,%9}, {%0,%1,%2,%3};"
        : "+f"(c[0]), "+f"(c[1]), "+f"(c[2]), "+f"(c[3])
        : "r"(a0), "r"(a1), "r"(a2), "r"(a3), "r"(b0), "r"(b1));
}

// split two floats into (hi,lo) bf16x2 packed u32 (x at low half = lower col)
__device__ __forceinline__ void cvt2(float x, float y, unsigned& hi, unsigned& lo) {
    __nv_bfloat16 xh = __float2bfloat16(x), yh = __float2bfloat16(y);
    __nv_bfloat16 xl = __float2bfloat16(x - __bfloat162float(xh));
    __nv_bfloat16 yl = __float2bfloat16(y - __bfloat162float(yh));
    hi = (unsigned)__bfloat16_as_ushort(xh) | ((unsigned)__bfloat16_as_ushort(yh) << 16);
    lo = (unsigned)__bfloat16_as_ushort(xl) | ((unsigned)__bfloat16_as_ushort(yl) << 16);
}

__global__ __launch_bounds__(TPB_T) void corr_mma(const float* __restrict__ q,
                                                  const float* __restrict__ k) {
    // 37,248 B: stage arrays (7680 u32) first, then reused as D[96][97] fp32
    __shared__ unsigned us[9312];
    unsigned* AhU = us;                 // [96][RS]
    unsigned* AlU = us + 1920;
    unsigned* BhU = us + 3840;
    unsigned* BlU = us + 5760;

    const int tid  = threadIdx.x;
    const int wid  = tid >> 5, lane = tid & 31;
    const int g    = lane >> 2, t4 = lane & 3;
    const int unit = blockIdx.x;        // (b*N_V+v)*4 + hc
    const int bv   = unit >> 2, hc = unit & 3;
    const int b = bv / N_V, v = bv % N_V;
    const int M0 = wid * 16;

    float acc[48];
#pragma unroll
    for (int i = 0; i < 48; ++i) acc[i] = 0.f;

    const size_t row0 = ((size_t)b * L_SEQ * N_V + v) * N_C;
    const size_t rstr = (size_t)N_V * N_C;

    for (int cc = 0; cc < 4; ++cc) {
        const int c0 = hc * 128 + cc * 32;
        // stage 96 rows x 32 channels: q -> Ah/Al, k -> Bh/Bl
#pragma unroll
        for (int it = 0; it < 4; ++it) {
            const int i = tid + it * TPB_T;
            const int row = i >> 3, f = i & 7;      // f: float4 group, cols 4f..4f+3
            const size_t off = row0 + (size_t)row * rstr + c0 + 4 * f;
            const float4 xq = *reinterpret_cast<const float4*>(q + off);
            const float4 xk = *reinterpret_cast<const float4*>(k + off);
            unsigned qh0, ql0, qh1, ql1, kh0, kl0, kh1, kl1;
            cvt2(xq.x, xq.y, qh0, ql0);
            cvt2(xq.z, xq.w, qh1, ql1);
            cvt2(xk.x, xk.y, kh0, kl0);
            cvt2(xk.z, xk.w, kh1, kl1);
            const int ub = row * RS + 2 * f;
            AhU[ub] = qh0; AhU[ub + 1] = qh1;
            AlU[ub] = ql0; AlU[ub + 1] = ql1;
            BhU[ub] = kh0; BhU[ub + 1] = kh1;
            BlU[ub] = kl0; BlU[ub + 1] = kl1;
        }
        __syncthreads();

#pragma unroll
        for (int kb = 0; kb < 2; ++kb) {            // two k16 blocks per 32-ch chunk
            const int ka = kb * 8 + t4;
            const unsigned ah0 = AhU[(M0 + g) * RS + ka];
            const unsigned ah1 = AhU[(M0 + g + 8) * RS + ka];
            const unsigned ah2 = AhU[(M0 + g) * RS + ka + 4];
            const unsigned ah3 = AhU[(M0 + g + 8) * RS + ka + 4];
            const unsigned al0 = AlU[(M0 + g) * RS + ka];
            const unsigned al1 = AlU[(M0 + g + 8) * RS + ka];
            const unsigned al2 = AlU[(M0 + g) * RS + ka + 4];
            const unsigned al3 = AlU[(M0 + g + 8) * RS + ka + 4];
#pragma unroll
            for (int nt = 0; nt < 12; ++nt) {
                const int bx = (nt * 8 + g) * RS + ka;
                const unsigned bh0 = BhU[bx], bh1 = BhU[bx + 4];
                const unsigned bl0 = BlU[bx], bl1 = BlU[bx + 4];
                float* c = acc + nt * 4;
                mma_bf16(c, ah0, ah1, ah2, ah3, bh0, bh1);   // hh
                mma_bf16(c, ah0, ah1, ah2, ah3, bl0, bl1);   // hl
                mma_bf16(c, al0, al1, al2, al3, bh0, bh1);   // lh
            }
        }
        __syncthreads();
    }

    // acc -> D[96][97] (reuse smem), then circular-diagonal reduce
    float* D = reinterpret_cast<float*>(us);
#pragma unroll
    for (int nt = 0; nt < 12; ++nt) {
        const int col = nt * 8 + 2 * t4;
        D[(M0 + g) * 97 + col]         = acc[nt * 4 + 0];
        D[(M0 + g) * 97 + col + 1]     = acc[nt * 4 + 1];
        D[(M0 + g + 8) * 97 + col]     = acc[nt * 4 + 2];
        D[(M0 + g + 8) * 97 + col + 1] = acc[nt * 4 + 3];
    }
    __syncthreads();
    if (tid < L_SEQ) {
        float s = 0.f;
        int col = (L_SEQ - tid) % L_SEQ;            // (t - l + 96)%96 at t=0
        for (int t = 0; t < L_SEQ; ++t) {
            s += D[t * 97 + col];
            col = (col + 1 == L_SEQ) ? 0 : col + 1;
        }
        g_mv4[(size_t)unit * L_SEQ + tid] = s;
    }
}

// ---------------------------------------------------------------------------
// Phase B: combine quarters, global mean over b, top-4 per v (ties -> lowest
// index, matching lax.top_k), softmax per (b,v). Tiny. (verbatim from R12)
// ---------------------------------------------------------------------------
__global__ void topk_kernel() {
    const int v = blockIdx.x;
    __shared__ float gm[L_SEQ];
    __shared__ int ids[TOPK];
    const int tid = threadIdx.x;
    if (tid < L_SEQ) {
        float s = 0.f;
        for (int b = 0; b < N_B; ++b) {
            const int u = (b * N_V + v) * N_UNITS;
#pragma unroll
            for (int r = 0; r < N_UNITS; ++r)
                s += g_mv4[(size_t)(u + r) * L_SEQ + tid];
        }
        gm[tid] = s;
    }
    __syncthreads();
    if (tid == 0) {
        for (int kk = 0; kk < TOPK; ++kk) {
            float best = -3.0e38f; int bi = 0;
            for (int l = 0; l < L_SEQ; ++l)
                if (gm[l] > best) { best = gm[l]; bi = l; }
            ids[kk] = bi;
            gm[bi] = -3.0e38f;
            g_idx[v * TOPK + kk] = bi;
        }
    }
    __syncthreads();
    if (tid < N_B) {
        const int b = tid;
        const int u = (b * N_V + v) * N_UNITS;
        float w[TOPK];
        float mx = -3.0e38f;
        for (int kk = 0; kk < TOPK; ++kk) {
            const int id = ids[kk];
            float s = 0.f;
#pragma unroll
            for (int r = 0; r < N_UNITS; ++r)
                s += g_mv4[(size_t)(u + r) * L_SEQ + id];
            w[kk] = s * (1.0f / 512.0f);
            mx = fmaxf(mx, w[kk]);
        }
        float se = 0.f;
        for (int kk = 0; kk < TOPK; ++kk) { w[kk] = expf(w[kk] - mx); se += w[kk]; }
        const float inv = 1.0f / se;
        for (int kk = 0; kk < TOPK; ++kk)
            g_prob[(b * N_V + v) * TOPK + kk] = w[kk] * inv;
    }
}

// ---------------------------------------------------------------------------
// Phase C: out[b,l,v,e,h] = sum_kk p * val[b,(l+idx_kk)%96,v,h,e].
// Read-once, one CTA per (b, v, e-octant); (h,e)->(e,h) transpose during
// staging; compute pass pure LDS.128 + FFMA + STG.128. (verbatim from R12)
// ---------------------------------------------------------------------------
#define TPB_G 256

__global__ __launch_bounds__(TPB_G) void agg_kernel(const float* __restrict__ val,
                                                    float* __restrict__ out) {
    __shared__ float s[L_SEQ * 64];
    const int blk = blockIdx.x;
    const int bv = blk >> 3;
    const int ep = blk & 7;
    const int b = bv / N_V, v = bv % N_V;
    const int e0 = ep * 8;
    const int tid = threadIdx.x;

    int idx[TOPK]; float p[TOPK];
#pragma unroll
    for (int kk = 0; kk < TOPK; ++kk) {
        idx[kk] = g_idx[v * TOPK + kk];
        p[kk]   = g_prob[(b * N_V + v) * TOPK + kk];
    }
    const size_t base = ((size_t)b * L_SEQ * N_V + v) * N_C;
    const size_t rstr = (size_t)N_V * N_C;

#pragma unroll
    for (int it = 0; it < 3072 / TPB_G; ++it) {
        const int j = tid + it * TPB_G;
        const int t = j >> 5;
        const int r = j & 31;
        const int h = r >> 2;
        const int e2 = (r & 3) * 2;
        const float2 x = *reinterpret_cast<const float2*>(
            val + base + (size_t)t * rstr + h * 64 + e0 + e2);
        s[t * 64 + e2 * 8 + h]       = x.x;
        s[t * 64 + (e2 + 1) * 8 + h] = x.y;
    }
    __syncthreads();

    const int co0 = (tid & 15) * 4;
    const int lz  = tid >> 4;

#pragma unroll
    for (int li = 0; li < L_SEQ / 16; ++li) {
        const int l = lz + li * 16;
        float4 r = make_float4(0.f, 0.f, 0.f, 0.f);
#pragma unroll
        for (int kk = 0; kk < TOPK; ++kk) {
            int t = l + idx[kk];
            if (t >= L_SEQ) t -= L_SEQ;
            const float4 x = *reinterpret_cast<const float4*>(&s[t * 64 + co0]);
            r.x += p[kk] * x.x; r.y += p[kk] * x.y;
            r.z += p[kk] * x.z; r.w += p[kk] * x.w;
        }
        *reinterpret_cast<float4*>(out + base + (size_t)l * rstr + e0 * 8 + co0) = r;
    }
}

extern "C" void kernel_launch(void* const* d_in, const int* in_sizes, int n_in,
                              void* d_out, int out_size) {
    const float* q  = (const float*)d_in[0];
    const float* k  = (const float*)d_in[1];
    const float* vv = (const float*)d_in[2];
    float* out = (float*)d_out;

    corr_mma<<<N_B * N_V * N_UNITS, TPB_T>>>(q, k);
    topk_kernel<<<N_V, 128>>>();
    agg_kernel<<<N_B * N_V * 8, TPB_G>>>(vv, out);
}